// round 8
// baseline (speedup 1.0000x reference)
#include <cuda_runtime.h>
#include <math.h>

// Two-kernel scheme:
//  k1 (1 warp): build the 4x4 SE3 exp-map matrix into a __device__ global.
//  k2 (streaming): pure load->FMA->store, no shared memory, no barrier —
//     matrix rows fetched via __ldg (uniform address, L1 broadcast).
// Rows 0..2 stored as (R_i0, R_i1, R_i2, t_i); row 3 is [0,0,0,1] so
// out row3 = x row3.

__device__ float4 g_M[3];

__global__ void se3_build_matrix(const float* __restrict__ w,
                                 const float* __restrict__ v,
                                 const float* __restrict__ theta_p) {
    if (threadIdx.x == 0) {
        const float wx = w[0], wy = w[1], wz = w[2];
        const float vx = v[0], vy = v[1], vz = v[2];
        const float th = theta_p[0];
        const float s = sinf(th);
        const float c = cosf(th);
        const float a = 1.0f - c;      // matches jax fp32: (1 - cos)
        const float b = th - s;        // matches jax fp32: (theta - sin)

        float K[3][3] = { {0.f, -wz,  wy},
                          { wz, 0.f, -wx},
                          {-wy,  wx, 0.f} };
        float KK[3][3];
        #pragma unroll
        for (int r = 0; r < 3; r++)
            #pragma unroll
            for (int j = 0; j < 3; j++)
                KK[r][j] = K[r][0]*K[0][j] + K[r][1]*K[1][j] + K[r][2]*K[2][j];

        float R[3][3], V[3][3];
        #pragma unroll
        for (int r = 0; r < 3; r++)
            #pragma unroll
            for (int j = 0; j < 3; j++) {
                const float I = (r == j) ? 1.0f : 0.0f;
                R[r][j] = I + s * K[r][j] + a * KK[r][j];
                V[r][j] = I * th + a * K[r][j] + b * KK[r][j];
            }

        float t0 = V[0][0]*vx + V[0][1]*vy + V[0][2]*vz;
        float t1 = V[1][0]*vx + V[1][1]*vy + V[1][2]*vz;
        float t2 = V[2][0]*vx + V[2][1]*vy + V[2][2]*vz;

        g_M[0] = make_float4(R[0][0], R[0][1], R[0][2], t0);
        g_M[1] = make_float4(R[1][0], R[1][1], R[1][2], t1);
        g_M[2] = make_float4(R[2][0], R[2][1], R[2][2], t2);
    }
}

// Streaming transform: 1 float4 column per thread, 4 front-batched LDG.128.cg,
// 4 STG.128.cs, no barrier. x/out are [4, N] row-major (n4 = N/4 float4 cols).
__global__ void __launch_bounds__(256, 6)
se3_transform(const float4* __restrict__ x, float4* __restrict__ out, int n4) {
    const unsigned i = blockIdx.x * blockDim.x + threadIdx.x;
    if (i >= (unsigned)n4) return;
    const size_t s1 = (size_t)n4;

    // Front-batch the 4 streaming loads.
    const float4 x0 = __ldcg(&x[i]);
    const float4 x1 = __ldcg(&x[i + s1]);
    const float4 x2 = __ldcg(&x[i + 2*s1]);
    const float4 x3 = __ldcg(&x[i + 3*s1]);

    // Matrix rows: uniform-address loads, L1/L2 broadcast.
    const float4 m0 = __ldg(&g_M[0]);
    const float4 m1 = __ldg(&g_M[1]);
    const float4 m2 = __ldg(&g_M[2]);

    float4 r0, r1, r2;
    r0.x = m0.x*x0.x + m0.y*x1.x + m0.z*x2.x + m0.w*x3.x;
    r0.y = m0.x*x0.y + m0.y*x1.y + m0.z*x2.y + m0.w*x3.y;
    r0.z = m0.x*x0.z + m0.y*x1.z + m0.z*x2.z + m0.w*x3.z;
    r0.w = m0.x*x0.w + m0.y*x1.w + m0.z*x2.w + m0.w*x3.w;

    r1.x = m1.x*x0.x + m1.y*x1.x + m1.z*x2.x + m1.w*x3.x;
    r1.y = m1.x*x0.y + m1.y*x1.y + m1.z*x2.y + m1.w*x3.y;
    r1.z = m1.x*x0.z + m1.y*x1.z + m1.z*x2.z + m1.w*x3.z;
    r1.w = m1.x*x0.w + m1.y*x1.w + m1.z*x2.w + m1.w*x3.w;

    r2.x = m2.x*x0.x + m2.y*x1.x + m2.z*x2.x + m2.w*x3.x;
    r2.y = m2.x*x0.y + m2.y*x1.y + m2.z*x2.y + m2.w*x3.y;
    r2.z = m2.x*x0.z + m2.y*x1.z + m2.z*x2.z + m2.w*x3.z;
    r2.w = m2.x*x0.w + m2.y*x1.w + m2.z*x2.w + m2.w*x3.w;

    __stcs(&out[i],        r0);
    __stcs(&out[i + s1],   r1);
    __stcs(&out[i + 2*s1], r2);
    __stcs(&out[i + 3*s1], x3);   // bottom row of M is [0,0,0,1]
}

extern "C" void kernel_launch(void* const* d_in, const int* in_sizes, int n_in,
                              void* d_out, int out_size) {
    const float* x     = (const float*)d_in[0];   // [4, N]
    const float* w     = (const float*)d_in[1];   // [3]
    const float* v     = (const float*)d_in[2];   // [3]
    const float* theta = (const float*)d_in[3];   // scalar

    const int N  = in_sizes[0] / 4;   // columns
    const int n4 = N / 4;             // float4 columns per row

    se3_build_matrix<<<1, 32>>>(w, v, theta);

    const int threads = 256;
    const int blocks  = (n4 + threads - 1) / threads;
    se3_transform<<<blocks, threads>>>((const float4*)x, (float4*)d_out, n4);
}

// round 9
// speedup vs baseline: 1.0282x; 1.0282x over previous
#include <cuda_runtime.h>
#include <math.h>

// Single kernel, zero synchronization: every thread builds the 4x4 SE3
// exp-map matrix itself (uniform-address scalar loads broadcast from L1;
// ~40 FMA + sin/cos, fully hidden under the DRAM latency of the 4
// front-batched x-loads). No shared memory, no barrier, one launch.
//
// x and out are [4, N] row-major; processed as float4 columns (n4 = N/4).
// Matrix rows 0..2 are (R_i0, R_i1, R_i2, t_i); row 3 is [0,0,0,1] so
// out row3 = x row3.

__device__ __forceinline__ void build_M(const float* __restrict__ w,
                                        const float* __restrict__ v,
                                        const float* __restrict__ theta_p,
                                        float4& m0, float4& m1, float4& m2) {
    const float wx = __ldg(&w[0]), wy = __ldg(&w[1]), wz = __ldg(&w[2]);
    const float vx = __ldg(&v[0]), vy = __ldg(&v[1]), vz = __ldg(&v[2]);
    const float th = __ldg(&theta_p[0]);
    const float s = sinf(th);
    const float c = cosf(th);
    const float a = 1.0f - c;      // matches jax fp32: (1 - cos)
    const float b = th - s;        // matches jax fp32: (theta - sin)

    float K[3][3] = { {0.f, -wz,  wy},
                      { wz, 0.f, -wx},
                      {-wy,  wx, 0.f} };
    float KK[3][3];
    #pragma unroll
    for (int r = 0; r < 3; r++)
        #pragma unroll
        for (int j = 0; j < 3; j++)
            KK[r][j] = K[r][0]*K[0][j] + K[r][1]*K[1][j] + K[r][2]*K[2][j];

    float R[3][3], V[3][3];
    #pragma unroll
    for (int r = 0; r < 3; r++)
        #pragma unroll
        for (int j = 0; j < 3; j++) {
            const float I = (r == j) ? 1.0f : 0.0f;
            R[r][j] = I + s * K[r][j] + a * KK[r][j];
            V[r][j] = I * th + a * K[r][j] + b * KK[r][j];
        }

    const float t0 = V[0][0]*vx + V[0][1]*vy + V[0][2]*vz;
    const float t1 = V[1][0]*vx + V[1][1]*vy + V[1][2]*vz;
    const float t2 = V[2][0]*vx + V[2][1]*vy + V[2][2]*vz;

    m0 = make_float4(R[0][0], R[0][1], R[0][2], t0);
    m1 = make_float4(R[1][0], R[1][1], R[1][2], t1);
    m2 = make_float4(R[2][0], R[2][1], R[2][2], t2);
}

__global__ void __launch_bounds__(256, 6)
se3_nosync(const float4* __restrict__ x, float4* __restrict__ out,
           const float* __restrict__ w, const float* __restrict__ v,
           const float* __restrict__ theta_p, int n4) {
    const unsigned i = blockIdx.x * blockDim.x + threadIdx.x;
    if (i >= (unsigned)n4) return;
    const size_t s1 = (size_t)n4;

    // Front-batch the 4 streaming loads first (independent of everything).
    const float4 x0 = __ldcg(&x[i]);
    const float4 x1 = __ldcg(&x[i + s1]);
    const float4 x2 = __ldcg(&x[i + 2*s1]);
    const float4 x3 = __ldcg(&x[i + 3*s1]);

    // Per-thread matrix build, overlapped with the load latency.
    float4 m0, m1, m2;
    build_M(w, v, theta_p, m0, m1, m2);

    float4 r0, r1, r2;
    r0.x = m0.x*x0.x + m0.y*x1.x + m0.z*x2.x + m0.w*x3.x;
    r0.y = m0.x*x0.y + m0.y*x1.y + m0.z*x2.y + m0.w*x3.y;
    r0.z = m0.x*x0.z + m0.y*x1.z + m0.z*x2.z + m0.w*x3.z;
    r0.w = m0.x*x0.w + m0.y*x1.w + m0.z*x2.w + m0.w*x3.w;

    r1.x = m1.x*x0.x + m1.y*x1.x + m1.z*x2.x + m1.w*x3.x;
    r1.y = m1.x*x0.y + m1.y*x1.y + m1.z*x2.y + m1.w*x3.y;
    r1.z = m1.x*x0.z + m1.y*x1.z + m1.z*x2.z + m1.w*x3.z;
    r1.w = m1.x*x0.w + m1.y*x1.w + m1.z*x2.w + m1.w*x3.w;

    r2.x = m2.x*x0.x + m2.y*x1.x + m2.z*x2.x + m2.w*x3.x;
    r2.y = m2.x*x0.y + m2.y*x1.y + m2.z*x2.y + m2.w*x3.y;
    r2.z = m2.x*x0.z + m2.y*x1.z + m2.z*x2.z + m2.w*x3.z;
    r2.w = m2.x*x0.w + m2.y*x1.w + m2.z*x2.w + m2.w*x3.w;

    __stcs(&out[i],        r0);
    __stcs(&out[i + s1],   r1);
    __stcs(&out[i + 2*s1], r2);
    __stcs(&out[i + 3*s1], x3);   // bottom row of M is [0,0,0,1]
}

extern "C" void kernel_launch(void* const* d_in, const int* in_sizes, int n_in,
                              void* d_out, int out_size) {
    const float* x     = (const float*)d_in[0];   // [4, N]
    const float* w     = (const float*)d_in[1];   // [3]
    const float* v     = (const float*)d_in[2];   // [3]
    const float* theta = (const float*)d_in[3];   // scalar

    const int N  = in_sizes[0] / 4;   // columns
    const int n4 = N / 4;             // float4 columns per row

    const int threads = 256;
    const int blocks  = (n4 + threads - 1) / threads;
    se3_nosync<<<blocks, threads>>>((const float4*)x, (float4*)d_out,
                                    w, v, theta, n4);
}